// round 1
// baseline (speedup 1.0000x reference)
#include <cuda_runtime.h>
#include <math.h>

#define B 256
#define T 512
#define F 128
#define H 256
#define H3 768

// Static device scratch for the hoisted input projection: MX[t*B+b][0..767]
__device__ float g_mx[(size_t)T * B * H3];   // ~402 MB, allowed (static __device__)

// ---------------------------------------------------------------------------
// Kernel 1: MX[m, n] = x[b, t, :] @ W[:, n] + bias_in[n],  m = t*B + b
// Tiled fp32 GEMM: 64x64 tile, BK=32, 256 threads, 4x4 microtile.
// ---------------------------------------------------------------------------
#define GM_BM 64
#define GM_BN 64
#define GM_BK 32

__global__ __launch_bounds__(256) void mx_gemm(const float* __restrict__ x,
                                               const float* __restrict__ w,
                                               const float* __restrict__ bias) {
    __shared__ float As[GM_BK][GM_BM + 4];   // [k][m], padded
    __shared__ float Bs[GM_BK][GM_BN];       // [k][n]

    const int bm = blockIdx.y * GM_BM;
    const int bn = blockIdx.x * GM_BN;
    const int tid = (int)threadIdx.x;
    const int tm = (tid >> 4) << 2;          // 0..60
    const int tn = (tid & 15) << 2;          // 0..60

    float acc[4][4] = {};

    for (int k0 = 0; k0 < F; k0 += GM_BK) {
        // Load A tile: 64 rows x 32 k, float4 along k, store transposed.
        #pragma unroll
        for (int i = 0; i < 2; i++) {
            int idx = tid + i * 256;         // 0..511
            int r = idx >> 3;                // 0..63
            int c = (idx & 7) << 2;          // 0,4,...,28
            int m = bm + r;
            int t = m >> 8;                  // m / B  (B = 256)
            int b = m & 255;                 // m % B
            float4 v = *(const float4*)&x[((size_t)b * T + t) * F + k0 + c];
            As[c + 0][r] = v.x;
            As[c + 1][r] = v.y;
            As[c + 2][r] = v.z;
            As[c + 3][r] = v.w;
        }
        // Load B tile: 32 k x 64 n.
        #pragma unroll
        for (int i = 0; i < 2; i++) {
            int idx = tid + i * 256;
            int r = idx >> 4;                // 0..31
            int c = (idx & 15) << 2;         // 0..60
            *(float4*)&Bs[r][c] = *(const float4*)&w[(size_t)(k0 + r) * H3 + bn + c];
        }
        __syncthreads();

        #pragma unroll
        for (int k = 0; k < GM_BK; k++) {
            float a0 = As[k][tm + 0];
            float a1 = As[k][tm + 1];
            float a2 = As[k][tm + 2];
            float a3 = As[k][tm + 3];
            float4 bv = *(const float4*)&Bs[k][tn];
            acc[0][0] += a0 * bv.x; acc[0][1] += a0 * bv.y; acc[0][2] += a0 * bv.z; acc[0][3] += a0 * bv.w;
            acc[1][0] += a1 * bv.x; acc[1][1] += a1 * bv.y; acc[1][2] += a1 * bv.z; acc[1][3] += a1 * bv.w;
            acc[2][0] += a2 * bv.x; acc[2][1] += a2 * bv.y; acc[2][2] += a2 * bv.z; acc[2][3] += a2 * bv.w;
            acc[3][0] += a3 * bv.x; acc[3][1] += a3 * bv.y; acc[3][2] += a3 * bv.z; acc[3][3] += a3 * bv.w;
        }
        __syncthreads();
    }

    const float bz0 = bias[bn + tn + 0];
    const float bz1 = bias[bn + tn + 1];
    const float bz2 = bias[bn + tn + 2];
    const float bz3 = bias[bn + tn + 3];
    #pragma unroll
    for (int i = 0; i < 4; i++) {
        float4 o;
        o.x = acc[i][0] + bz0;
        o.y = acc[i][1] + bz1;
        o.z = acc[i][2] + bz2;
        o.w = acc[i][3] + bz3;
        *(float4*)&g_mx[(size_t)(bm + tm + i) * H3 + bn + tn] = o;
    }
}

// ---------------------------------------------------------------------------
// Kernel 2: one GRU step.
//   mh = hprev @ Wr (+ rec_bias applied in epilogue)
//   z = sigmoid(mxz + mhz); r = sigmoid(mxr + mhr); c = tanh(mxh + r*mhh)
//   hout = z*hprev + (1-z)*c
// Tile: 16 batch x 32 hidden per block, 128 threads (1b x 4j per thread).
// Grid: (H/32=8, B/16=16) = 128 blocks.
// hprev == nullptr means h = 0 (step 0).
// ---------------------------------------------------------------------------
#define SB 16
#define SJ 32
#define SK 32

__device__ __forceinline__ float sigmoidf_(float v) {
    return 1.0f / (1.0f + __expf(-v));
}

__global__ __launch_bounds__(128) void gru_step(const float* __restrict__ hprev,
                                                const float* __restrict__ mx_t,
                                                const float* __restrict__ wr,
                                                const float* __restrict__ rbias,
                                                float* __restrict__ hout) {
    __shared__ float hs[SB][SK + 4];         // [b][k], padded (stride 36: 4-bank skew, 16B aligned)
    __shared__ float ws[3][SK][SJ];          // [gate][k][j]

    const int tid = (int)threadIdx.x;        // 0..127
    const int b0 = blockIdx.y * SB;
    const int j0 = blockIdx.x * SJ;
    const int bq = tid >> 3;                 // 0..15
    const int jq = (tid & 7) << 2;           // 0,4,...,28

    float accz[4] = {}, accr[4] = {}, acch[4] = {};

    for (int k0 = 0; k0 < H; k0 += SK) {
        // Load h tile: 16 x 32 floats, 1 float4 per thread.
        {
            int r = tid >> 3;                // 0..15
            int c = (tid & 7) << 2;          // 0..28
            float4 v;
            if (hprev) {
                v = *(const float4*)&hprev[(size_t)(b0 + r) * H + k0 + c];
            } else {
                v = make_float4(0.f, 0.f, 0.f, 0.f);
            }
            *(float4*)&hs[r][c] = v;
        }
        // Load Wr tiles for 3 gates: 3 * 32 * 32 floats = 768 float4, 6 per thread.
        #pragma unroll
        for (int i = 0; i < 6; i++) {
            int idx = tid + i * 128;         // 0..767
            int g = idx >> 8;                // 0..2
            int rem = idx & 255;
            int r = rem >> 3;                // k 0..31
            int c = (rem & 7) << 2;          // j 0..28
            *(float4*)&ws[g][r][c] =
                *(const float4*)&wr[(size_t)(k0 + r) * H3 + g * H + j0 + c];
        }
        __syncthreads();

        #pragma unroll
        for (int k = 0; k < SK; k++) {
            float hv = hs[bq][k];
            float4 wz = *(const float4*)&ws[0][k][jq];
            float4 wv = *(const float4*)&ws[1][k][jq];
            float4 wh = *(const float4*)&ws[2][k][jq];
            accz[0] += hv * wz.x; accz[1] += hv * wz.y; accz[2] += hv * wz.z; accz[3] += hv * wz.w;
            accr[0] += hv * wv.x; accr[1] += hv * wv.y; accr[2] += hv * wv.z; accr[3] += hv * wv.w;
            acch[0] += hv * wh.x; acch[1] += hv * wh.y; acch[2] += hv * wh.z; acch[3] += hv * wh.w;
        }
        __syncthreads();
    }

    const int b = b0 + bq;
    const int j = j0 + jq;
    // mx row for this batch element
    const float* mxr = mx_t + (size_t)b * H3;

    float4 xz = *(const float4*)&mxr[j];
    float4 xr = *(const float4*)&mxr[H + j];
    float4 xh = *(const float4*)&mxr[2 * H + j];
    float4 bzv = *(const float4*)&rbias[j];
    float4 brv = *(const float4*)&rbias[H + j];
    float4 bhv = *(const float4*)&rbias[2 * H + j];

    float hp[4];
    if (hprev) {
        float4 hv = *(const float4*)&hprev[(size_t)b * H + j];
        hp[0] = hv.x; hp[1] = hv.y; hp[2] = hv.z; hp[3] = hv.w;
    } else {
        hp[0] = hp[1] = hp[2] = hp[3] = 0.f;
    }

    float xzv[4] = {xz.x, xz.y, xz.z, xz.w};
    float xrv[4] = {xr.x, xr.y, xr.z, xr.w};
    float xhv[4] = {xh.x, xh.y, xh.z, xh.w};
    float bz[4] = {bzv.x, bzv.y, bzv.z, bzv.w};
    float br[4] = {brv.x, brv.y, brv.z, brv.w};
    float bh[4] = {bhv.x, bhv.y, bhv.z, bhv.w};

    float4 o;
    float out4[4];
    #pragma unroll
    for (int jj = 0; jj < 4; jj++) {
        float z = sigmoidf_(xzv[jj] + accz[jj] + bz[jj]);
        float r = sigmoidf_(xrv[jj] + accr[jj] + br[jj]);
        float hh = acch[jj] + bh[jj];
        float c = tanhf(xhv[jj] + r * hh);
        out4[jj] = z * hp[jj] + (1.0f - z) * c;
    }
    o.x = out4[0]; o.y = out4[1]; o.z = out4[2]; o.w = out4[3];
    *(float4*)&hout[(size_t)b * H + j] = o;
}

// ---------------------------------------------------------------------------
// Launch: one GEMM + 512 chained step kernels (graph-capturable).
// Step t writes its hidden state directly into the output slice out[t];
// step t+1 reads it back as hprev. out layout: (T, B, H).
// ---------------------------------------------------------------------------
extern "C" void kernel_launch(void* const* d_in, const int* in_sizes, int n_in,
                              void* d_out, int out_size) {
    (void)in_sizes; (void)n_in; (void)out_size;
    const float* x    = (const float*)d_in[0];   // (B, T, F)
    const float* w    = (const float*)d_in[1];   // (F, 3H)
    const float* wr   = (const float*)d_in[2];   // (H, 3H)
    const float* bias = (const float*)d_in[3];   // (2, 3H)
    float* out = (float*)d_out;                  // (T, B, H)

    float* mx;
    cudaGetSymbolAddress((void**)&mx, g_mx);

    dim3 g1(H3 / GM_BN, (T * B) / GM_BM);        // (12, 2048)
    mx_gemm<<<g1, 256>>>(x, w, bias);

    const float* rbias = bias + H3;              // recurrent bias
    dim3 g2(H / SJ, B / SB);                     // (8, 16) = 128 blocks

    for (int t = 0; t < T; t++) {
        const float* hprev = (t == 0) ? nullptr : out + (size_t)(t - 1) * B * H;
        gru_step<<<g2, 128>>>(hprev,
                              mx + (size_t)t * B * H3,
                              wr,
                              rbias,
                              out + (size_t)t * B * H);
    }
}